// round 14
// baseline (speedup 1.0000x reference)
#include <cuda_runtime.h>

typedef unsigned long long ull;

__device__ __forceinline__ ull pk2(float a, float b) {
    ull r; asm("mov.b64 %0,{%1,%2};" : "=l"(r) : "f"(a), "f"(b)); return r;
}
__device__ __forceinline__ void upk2(ull v, float& a, float& b) {
    asm("mov.b64 {%0,%1},%2;" : "=f"(a), "=f"(b) : "l"(v));
}
__device__ __forceinline__ ull mul2(ull a, ull b) {
    ull r; asm("mul.rn.f32x2 %0,%1,%2;" : "=l"(r) : "l"(a), "l"(b)); return r;
}
__device__ __forceinline__ ull add2(ull a, ull b) {
    ull r; asm("add.rn.f32x2 %0,%1,%2;" : "=l"(r) : "l"(a), "l"(b)); return r;
}
__device__ __forceinline__ ull fma2(ull a, ull b, ull c) {
    ull r; asm("fma.rn.f32x2 %0,%1,%2,%3;" : "=l"(r) : "l"(a), "l"(b), "l"(c)); return r;
}

extern __shared__ ull sgrid[];  // NG * 10 ull: 8 dup'd grid coords, dup'd -norm, pad

// Exact-double argmax rescan (rare: fp32 near-tie rows only).
__device__ __noinline__ int rescan_double(const float* __restrict__ grid,
                                          const float* __restrict__ gnorm,
                                          const float* ya, int NG)
{
    double best = -1e300;
    int q = 0;
    double yd[8];
    #pragma unroll
    for (int i = 0; i < 8; i++) yd[i] = (double)ya[i];
    for (int g = 0; g < NG; g++) {
        const float* gp = grid + g * 8;
        double s = 0.0;
        #pragma unroll
        for (int i = 0; i < 8; i++) s = fma(yd[i], (double)gp[i], s);
        s = 2.0 * s - (double)gnorm[g];
        if (s > best) { best = s; q = g; }
    }
    return q;
}

__global__ __launch_bounds__(512, 2)
void e8p_kernel(const float* __restrict__ X,
                const float* __restrict__ grid,
                const float* __restrict__ gnorm,
                const int* __restrict__ allcombo,
                float* __restrict__ out,
                int N, int NG, int ac_stride)
{
    for (int g = threadIdx.x; g < NG; g += blockDim.x) {
        const float* gp = grid + g * 8;
        ull* sp = sgrid + g * 10;
        #pragma unroll
        for (int i = 0; i < 8; i++) { float v = gp[i]; sp[i] = pk2(v, v); }
        float nn = -gnorm[g];
        sp[8] = pk2(nn, nn);
        sp[9] = 0ull;
    }
    __syncthreads();

    int r = blockIdx.x * blockDim.x + threadIdx.x;
    if (r >= N) return;

    const float4* xp = (const float4*)(X + (size_t)r * 8);
    float4 xa = xp[0], xb = xp[1];
    float x[8] = {xa.x, xa.y, xa.z, xa.w, xb.x, xb.y, xb.z, xb.w};

    // Build Ya for both parts (P: X+0.25, M: X-0.25), pack as (P, M) f32x2.
    unsigned nbP = 0, nbM = 0;
    ull ya[8];
    float yaPs[8], yaMs[8];
    {
        float yP[8], yM[8];
        #pragma unroll
        for (int i = 0; i < 8; i++) {
            yP[i] = __fadd_rn(x[i], 0.25f);
            yM[i] = __fadd_rn(x[i], -0.25f);
            if (yP[i] < 0.f) nbP |= 1u << i;
            if (yM[i] < 0.f) nbM |= 1u << i;
        }
        unsigned oddP = __popc(nbP) & 1u;
        unsigned oddM = __popc(nbM) & 1u;
        #pragma unroll
        for (int i = 0; i < 8; i++) {
            float aP = fabsf(yP[i]), aM = fabsf(yM[i]);
            if (i == 0) {
                if (oddP) aP = -aP;
                if (oddM) aM = -aM;
            }
            yaPs[i] = aP; yaMs[i] = aM;
            ya[i] = pk2(aP, aM);
        }
    }

    // Packed fp32 argmax of 2*Ya.g - |g|^2 with runner-up tracking.
    float bP = -3.4e38f, bM = -3.4e38f;
    float b2P = -3.4e38f, b2M = -3.4e38f;
    int qP = 0, qM = 0;
    #pragma unroll 4
    for (int g = 0; g < NG; g++) {
        const ulonglong2* p = (const ulonglong2*)(sgrid + g * 10);
        ulonglong2 c0 = p[0], c1 = p[1], c2 = p[2], c3 = p[3], c4 = p[4];
        ull s = mul2(ya[0], c0.x);
        s = fma2(ya[1], c0.y, s);
        s = fma2(ya[2], c1.x, s);
        s = fma2(ya[3], c1.y, s);
        s = fma2(ya[4], c2.x, s);
        s = fma2(ya[5], c2.y, s);
        s = fma2(ya[6], c3.x, s);
        s = fma2(ya[7], c3.y, s);
        s = add2(s, s);
        s = add2(s, c4.x);
        float sp, sm;
        upk2(s, sp, sm);
        if (sp > bP) { b2P = bP; bP = sp; qP = g; }
        else if (sp > b2P) { b2P = sp; }
        if (sm > bM) { b2M = bM; bM = sm; qM = g; }
        else if (sm > b2M) { b2M = sm; }
    }
    float thr = 1e-4f;
    if (__fadd_rn(bP, -b2P) < thr * fmaxf(1.f, fabsf(bP)))
        qP = rescan_double(grid, gnorm, yaPs, NG);
    if (__fadd_rn(bM, -b2M) < thr * fmaxf(1.f, fabsf(bM)))
        qM = rescan_double(grid, gnorm, yaMs, NG);

    // Epilogue.
    unsigned oddP = __popc(nbP) & 1u;
    unsigned oddM = __popc(nbM) & 1u;
    unsigned mbP = nbP ^ oddP;
    unsigned mbM = nbM ^ oddM;

    // idx_map[mint] == rank of even-parity byte mint among even-parity
    // bytes == mint >> 1 (each consecutive byte pair {2k,2k+1} holds exactly
    // one even-parity byte). Closed form — idx_map table read eliminated.
    unsigned mintP = __brev(mbP) >> 24;
    unsigned mintM = __brev(mbM) >> 24;
    int rowP = (int)(mintP >> 1);
    int rowM = (int)(mintM >> 1);

    // allcombo stride from runtime size (in_sizes[3] / 128), not assumed NG.
    int realP = allcombo[rowP * ac_stride + qP];
    int realM = allcombo[rowM * ac_stride + qM];

    const float* gP = grid + qP * 8;
    const float* gM = grid + qM * 8;
    float vP[8], vM[8];
    double eP2 = 0.0, eM2 = 0.0;
    #pragma unroll
    for (int i = 0; i < 8; i++) {
        float yPi = __fadd_rn(x[i], 0.25f);
        float yMi = __fadd_rn(x[i], -0.25f);
        float gvP = gP[i];
        if ((mbP >> i) & 1u) gvP = -gvP;
        vP[i] = gvP;
        double dP = (double)yPi - (double)gvP;
        eP2 = fma(dP, dP, eP2);
        float gvM = gM[i];
        if ((mbM >> i) & 1u) gvM = -gvM;
        vM[i] = gvM;
        double dM = (double)yMi - (double)gvM;
        eM2 = fma(dM, dM, eM2);
    }
    float eP = __fsqrt_rn((float)eP2);
    float eM = __fsqrt_rn((float)eM2);
    bool which = eP < eM;

    float ov[8];
    #pragma unroll
    for (int i = 0; i < 8; i++)
        ov[i] = which ? __fadd_rn(vP[i], -0.25f) : __fadd_rn(vM[i], 0.25f);

    float4* outp = (float4*)(out + (size_t)r * 8);
    outp[0] = make_float4(ov[0], ov[1], ov[2], ov[3]);
    outp[1] = make_float4(ov[4], ov[5], ov[6], ov[7]);

    // Output 1: grid_idx_map[k] == int16(k - 32768) in closed form (gim
    // table read eliminated; 16-bit mask reproduces the table's wrap for
    // any sel). Stored as float32 at element offset 8N (format indicated
    // by the R11/R12 evidence pair).
    int sel = which ? (realP + 32768) : realM;
    sel &= 0xFFFF;
    short iv = (short)(sel - 32768);
    out[(size_t)N * 8 + r] = (float)iv;
}

extern "C" void kernel_launch(void* const* d_in, const int* in_sizes, int n_in,
                              void* d_out, int out_size)
{
    const float* X        = (const float*)d_in[0];
    const float* grid     = (const float*)d_in[1];
    const float* gnorm    = (const float*)d_in[2];
    const int*   allcombo = (const int*)d_in[3];
    // d_in[4] idx_map, d_in[5] int_map, d_in[6] grid_idx_map: replaced by
    // closed forms (mint>>1 and k-32768).

    int N  = in_sizes[0] / 8;
    int NG = in_sizes[2];
    int ac_stride = in_sizes[3] / 128;   // allcombo_idx is (128, stride)

    size_t smem = (size_t)NG * 10 * sizeof(unsigned long long);
    cudaFuncSetAttribute(e8p_kernel, cudaFuncAttributeMaxDynamicSharedMemorySize,
                         (int)smem);

    int threads = 512;
    int blocks = (N + threads - 1) / threads;
    e8p_kernel<<<blocks, threads, smem>>>(X, grid, gnorm, allcombo,
                                          (float*)d_out, N, NG, ac_stride);
}

// round 16
// speedup vs baseline: 8.8495x; 8.8495x over previous
#include <cuda_runtime.h>

typedef unsigned long long ull;

__device__ __forceinline__ ull pk2(float a, float b) {
    ull r; asm("mov.b64 %0,{%1,%2};" : "=l"(r) : "f"(a), "f"(b)); return r;
}
__device__ __forceinline__ void upk2(ull v, float& a, float& b) {
    asm("mov.b64 {%0,%1},%2;" : "=f"(a), "=f"(b) : "l"(v));
}
__device__ __forceinline__ ull mul2(ull a, ull b) {
    ull r; asm("mul.rn.f32x2 %0,%1,%2;" : "=l"(r) : "l"(a), "l"(b)); return r;
}
__device__ __forceinline__ ull add2(ull a, ull b) {
    ull r; asm("add.rn.f32x2 %0,%1,%2;" : "=l"(r) : "l"(a), "l"(b)); return r;
}
__device__ __forceinline__ ull fma2(ull a, ull b, ull c) {
    ull r; asm("fma.rn.f32x2 %0,%1,%2,%3;" : "=l"(r) : "l"(a), "l"(b), "l"(c)); return r;
}

extern __shared__ ull sgrid[];  // NG * 10 ull: 8 dup'd grid coords, dup'd -norm, pad

// Near-tie resolution, shortlist version. Walks all candidates in cheap
// scalar fp32 (fed from SMEM lo lanes), and evaluates EXACT double scores
// only for candidates within `thr` of the fp32 best. The true double
// argmax provably lies in that shortlist (fp32 score error << thr/2), so
// this returns the same index as a full double rescan, first-index ties.
// Cost: ~12 fp32 ops/candidate + a handful of rare double evals — no more
// serial-DFMA straggler tails.
__device__ __noinline__ int rescan_shortlist(const float* ya, float bbest,
                                             float thr, int NG)
{
    const float* sg = (const float*)sgrid;   // lo lanes of packed layout
    float cutoff = __fadd_rn(bbest, -thr);
    double yd[8];
    #pragma unroll
    for (int i = 0; i < 8; i++) yd[i] = (double)ya[i];
    double best_d = -1e300;
    int q = 0;
    for (int g = 0; g < NG; g++) {
        const float* row = sg + g * 20;      // stride 10 ull = 20 floats
        float s = __fmul_rn(ya[0], row[0]);
        s = __fmaf_rn(ya[1], row[2],  s);
        s = __fmaf_rn(ya[2], row[4],  s);
        s = __fmaf_rn(ya[3], row[6],  s);
        s = __fmaf_rn(ya[4], row[8],  s);
        s = __fmaf_rn(ya[5], row[10], s);
        s = __fmaf_rn(ya[6], row[12], s);
        s = __fmaf_rn(ya[7], row[14], s);
        s = __fadd_rn(s, s);
        s = __fadd_rn(s, row[16]);           // + (-norm)
        if (s >= cutoff) {
            double sd = 0.0;
            #pragma unroll
            for (int i = 0; i < 8; i++)
                sd = fma(yd[i], (double)row[2 * i], sd);
            sd = 2.0 * sd + (double)row[16];
            if (sd > best_d) { best_d = sd; q = g; }
        }
    }
    return q;
}

__global__ __launch_bounds__(512, 2)
void e8p_kernel(const float* __restrict__ X,
                const float* __restrict__ grid,
                const float* __restrict__ gnorm,
                const int* __restrict__ allcombo,
                float* __restrict__ out,
                int N, int NG, int ac_stride)
{
    for (int g = threadIdx.x; g < NG; g += blockDim.x) {
        const float* gp = grid + g * 8;
        ull* sp = sgrid + g * 10;
        #pragma unroll
        for (int i = 0; i < 8; i++) { float v = gp[i]; sp[i] = pk2(v, v); }
        float nn = -gnorm[g];
        sp[8] = pk2(nn, nn);
        sp[9] = 0ull;
    }
    __syncthreads();

    int r = blockIdx.x * blockDim.x + threadIdx.x;
    if (r >= N) return;

    const float4* xp = (const float4*)(X + (size_t)r * 8);
    float4 xa = xp[0], xb = xp[1];
    float x[8] = {xa.x, xa.y, xa.z, xa.w, xb.x, xb.y, xb.z, xb.w};

    // Build Ya for both parts (P: X+0.25, M: X-0.25), pack as (P, M) f32x2.
    unsigned nbP = 0, nbM = 0;
    ull ya[8];
    float yaPs[8], yaMs[8];
    {
        float yP[8], yM[8];
        #pragma unroll
        for (int i = 0; i < 8; i++) {
            yP[i] = __fadd_rn(x[i], 0.25f);
            yM[i] = __fadd_rn(x[i], -0.25f);
            if (yP[i] < 0.f) nbP |= 1u << i;
            if (yM[i] < 0.f) nbM |= 1u << i;
        }
        unsigned oddP = __popc(nbP) & 1u;
        unsigned oddM = __popc(nbM) & 1u;
        #pragma unroll
        for (int i = 0; i < 8; i++) {
            float aP = fabsf(yP[i]), aM = fabsf(yM[i]);
            if (i == 0) {
                if (oddP) aP = -aP;
                if (oddM) aM = -aM;
            }
            yaPs[i] = aP; yaMs[i] = aM;
            ya[i] = pk2(aP, aM);
        }
    }

    // Packed fp32 argmax of 2*Ya.g - |g|^2 with runner-up tracking.
    float bP = -3.4e38f, bM = -3.4e38f;
    float b2P = -3.4e38f, b2M = -3.4e38f;
    int qP = 0, qM = 0;
    #pragma unroll 4
    for (int g = 0; g < NG; g++) {
        const ulonglong2* p = (const ulonglong2*)(sgrid + g * 10);
        ulonglong2 c0 = p[0], c1 = p[1], c2 = p[2], c3 = p[3], c4 = p[4];
        ull s = mul2(ya[0], c0.x);
        s = fma2(ya[1], c0.y, s);
        s = fma2(ya[2], c1.x, s);
        s = fma2(ya[3], c1.y, s);
        s = fma2(ya[4], c2.x, s);
        s = fma2(ya[5], c2.y, s);
        s = fma2(ya[6], c3.x, s);
        s = fma2(ya[7], c3.y, s);
        s = add2(s, s);
        s = add2(s, c4.x);
        float sp, sm;
        upk2(s, sp, sm);
        if (sp > bP) { b2P = bP; bP = sp; qP = g; }
        else if (sp > b2P) { b2P = sp; }
        if (sm > bM) { b2M = bM; bM = sm; qM = g; }
        else if (sm > b2M) { b2M = sm; }
    }
    // Near-tie? Resolve exactly (same thresholds and semantics as R14's
    // full double rescan, via the provably-equivalent shortlist).
    float thrP = 1e-4f * fmaxf(1.f, fabsf(bP));
    float thrM = 1e-4f * fmaxf(1.f, fabsf(bM));
    if (__fadd_rn(bP, -b2P) < thrP)
        qP = rescan_shortlist(yaPs, bP, thrP, NG);
    if (__fadd_rn(bM, -b2M) < thrM)
        qM = rescan_shortlist(yaMs, bM, thrM, NG);

    // Epilogue.
    unsigned oddP = __popc(nbP) & 1u;
    unsigned oddM = __popc(nbM) & 1u;
    unsigned mbP = nbP ^ oddP;
    unsigned mbM = nbM ^ oddM;

    // idx_map[mint] == mint >> 1 (one even-parity byte per consecutive pair).
    unsigned mintP = __brev(mbP) >> 24;
    unsigned mintM = __brev(mbM) >> 24;
    int rowP = (int)(mintP >> 1);
    int rowM = (int)(mintM >> 1);

    int realP = allcombo[rowP * ac_stride + qP];
    int realM = allcombo[rowM * ac_stride + qM];

    const float* gP = grid + qP * 8;
    const float* gM = grid + qM * 8;
    float vP[8], vM[8];
    // Exact-double error sums (validated bit-exact in R11/R14).
    double eP2 = 0.0, eM2 = 0.0;
    #pragma unroll
    for (int i = 0; i < 8; i++) {
        float yPi = __fadd_rn(x[i], 0.25f);
        float yMi = __fadd_rn(x[i], -0.25f);
        float gvP = gP[i];
        if ((mbP >> i) & 1u) gvP = -gvP;
        vP[i] = gvP;
        double dP = (double)yPi - (double)gvP;
        eP2 = fma(dP, dP, eP2);
        float gvM = gM[i];
        if ((mbM >> i) & 1u) gvM = -gvM;
        vM[i] = gvM;
        double dM = (double)yMi - (double)gvM;
        eM2 = fma(dM, dM, eM2);
    }
    float eP = __fsqrt_rn((float)eP2);
    float eM = __fsqrt_rn((float)eM2);
    bool which = eP < eM;

    float ov[8];
    #pragma unroll
    for (int i = 0; i < 8; i++)
        ov[i] = which ? __fadd_rn(vP[i], -0.25f) : __fadd_rn(vM[i], 0.25f);

    float4* outp = (float4*)(out + (size_t)r * 8);
    outp[0] = make_float4(ov[0], ov[1], ov[2], ov[3]);
    outp[1] = make_float4(ov[4], ov[5], ov[6], ov[7]);

    // Output 1: grid_idx_map[k] == int16(k - 32768), stored widened to f32
    // at element offset 8N (validated in R14).
    int sel = which ? (realP + 32768) : realM;
    sel &= 0xFFFF;
    short iv = (short)(sel - 32768);
    out[(size_t)N * 8 + r] = (float)iv;
}

extern "C" void kernel_launch(void* const* d_in, const int* in_sizes, int n_in,
                              void* d_out, int out_size)
{
    const float* X        = (const float*)d_in[0];
    const float* grid     = (const float*)d_in[1];
    const float* gnorm    = (const float*)d_in[2];
    const int*   allcombo = (const int*)d_in[3];

    int N  = in_sizes[0] / 8;
    int NG = in_sizes[2];
    int ac_stride = in_sizes[3] / 128;   // allcombo_idx is (128, stride)

    size_t smem = (size_t)NG * 10 * sizeof(unsigned long long);
    cudaFuncSetAttribute(e8p_kernel, cudaFuncAttributeMaxDynamicSharedMemorySize,
                         (int)smem);

    int threads = 512;
    int blocks = (N + threads - 1) / threads;
    e8p_kernel<<<blocks, threads, smem>>>(X, grid, gnorm, allcombo,
                                          (float*)d_out, N, NG, ac_stride);
}